// round 17
// baseline (speedup 1.0000x reference)
#include <cuda_runtime.h>
#include <cuda_fp16.h>

#define NN 1024
#define DIM 128
#define HH 4
#define I_TILE 8
#define LOG2E 1.4426950408889634f

typedef unsigned long long u64;
typedef unsigned int u32;

// Scratch (device globals: no allocations allowed)
__device__ __half g_Lh[NN * DIM];          // fp16 L, row-major [i][head*32+d]
__device__ __half g_Rh[NN * DIM];          // fp16 R, [head*4+qg][j][8 halves]
__device__ u32    g_Vf[NN * DIM / 2];      // fp16 V in HMMA B-fragment order
__device__ float  g_La6[NN * HH];          // 0.6*log2e * sum_d a_d*L
__device__ float  g_Ra6[NN * HH];

#define HADD2(d, x, y) \
    asm("add.rn.f16x2 %0, %1, %2;" : "=r"(d) : "r"(x), "r"(y))
#define HFMA2(acc, m, x) \
    asm("fma.rn.f16x2 %0, %1, %2, %0;" : "+r"(acc) : "r"(m), "r"(x))
#define MMA16816(d0, d1, d2, d3, a0, a1, a2, a3, b0, b1) \
    asm volatile("mma.sync.aligned.m16n8k16.row.col.f32.f16.f16.f32 " \
                 "{%0,%1,%2,%3}, {%4,%5,%6,%7}, {%8,%9}, {%0,%1,%2,%3};" \
                 : "+f"(d0), "+f"(d1), "+f"(d2), "+f"(d3) \
                 : "r"(a0), "r"(a1), "r"(a2), "r"(a3), "r"(b0), "r"(b1))

// ---------------------------------------------------------------------------
// Prep: 256 threads/CTA, 16 rows/CTA, W fully staged in dynamic smem (64KB).
// tid = (half, col): threads 0-127 handle rows [0,8), 128-255 rows [8,16).
// Per-thread: 8 accumulators, 1024 FFMA; 8 warps/CTA; 2 CTAs/SM co-resident
// (144KB smem) -> all 192 CTAs in one wave.
// y=0: Lh = fp16(h@W_l); y=1: Rh transposed; y=2: Vf (B-fragment order);
// plus La6/Ra6 (pre-scaled by 0.6*log2e). Grid (64, 3), block 256.
// Dynamic smem: W_s[128*128] fp32 (64KB) + h_s[16*128] fp32 (8KB) = 72KB.
// ---------------------------------------------------------------------------
__global__ __launch_bounds__(256) void prep_kernel(
    const float* __restrict__ h,
    const float* __restrict__ Wl,
    const float* __restrict__ Wr,
    const float* __restrict__ Wv,
    const float* __restrict__ a)
{
    extern __shared__ float smem[];
    float* W_s = smem;                 // [128][128]
    float* h_s = smem + DIM * DIM;     // [16][128]

    int which = blockIdx.y;
    int tid  = threadIdx.x;
    int half = tid >> 7;               // row-half: 0 -> rows 0..7, 1 -> 8..15
    int col  = tid & 127;
    const float* W = (which == 0) ? Wl : (which == 1) ? Wr : Wv;
    int i0 = blockIdx.x * 16;

    // stage W (4096 float4; 16/thread) + h (512 float4; 2/thread)
    {
        const float4* W4 = reinterpret_cast<const float4*>(W);
        float4* Ws4 = reinterpret_cast<float4*>(W_s);
#pragma unroll
        for (int q = 0; q < 16; q++)
            Ws4[tid + q * 256] = __ldg(&W4[tid + q * 256]);
        const float4* h4g = reinterpret_cast<const float4*>(h + i0 * DIM);
        float4* hs4 = reinterpret_cast<float4*>(h_s);
#pragma unroll
        for (int q = 0; q < 2; q++)
            hs4[tid + q * 256] = __ldg(&h4g[tid + q * 256]);
    }
    __syncthreads();

    float acc[8];
#pragma unroll
    for (int r = 0; r < 8; r++) acc[r] = 0.f;

    const float4* h4 = reinterpret_cast<const float4*>(h_s) + half * 8 * 32;
#pragma unroll 4
    for (int k4 = 0; k4 < 32; k4++) {
        float w0 = W_s[(k4 * 4 + 0) * DIM + col];
        float w1 = W_s[(k4 * 4 + 1) * DIM + col];
        float w2 = W_s[(k4 * 4 + 2) * DIM + col];
        float w3 = W_s[(k4 * 4 + 3) * DIM + col];
#pragma unroll
        for (int r = 0; r < 8; r++) {
            float4 hv = h4[r * 32 + k4];
            acc[r] += hv.x * w0 + hv.y * w1 + hv.z * w2 + hv.w * w3;
        }
    }

    int head = col >> 5, d = col & 31;
    int r0 = half * 8;                 // first global row of this thread
    if (which == 0) {
#pragma unroll
        for (int r = 0; r < 8; r++)
            g_Lh[(i0 + r0 + r) * DIM + col] = __float2half_rn(acc[r]);
    } else if (which == 1) {
        int qg = d >> 3, slot = d & 7;
        __half* base = &g_Rh[(size_t)((head * 4 + qg) * NN) * 8 + slot];
#pragma unroll
        for (int r = 0; r < 8; r++)
            base[(i0 + r0 + r) * 8] = __float2half_rn(acc[r]);
    } else {
        // B-fragment store: CTA covers 16-j block jb = blockIdx.x.
        // This thread's rows are j-subrange regsel = half.
        int dt = d >> 3, n = d & 7;
        int jb = blockIdx.x;
#pragma unroll
        for (int m = 0; m < 4; m++) {
            __half2 hp = __floats2half2_rn(acc[2 * m], acc[2 * m + 1]);
            g_Vf[(((head * 64 + jb) * 4 + dt) * 32 + 4 * n + m) * 2 + half] =
                *reinterpret_cast<u32*>(&hp);
        }
    }

    if (which < 2) {
        float av = 0.6f * LOG2E * __ldg(&a[d]);
        float* A6 = (which == 0) ? g_La6 : g_Ra6;
#pragma unroll
        for (int r = 0; r < 8; r++) {
            float v = av * acc[r];
#pragma unroll
            for (int o = 16; o; o >>= 1) v += __shfl_xor_sync(0xffffffffu, v, o);
            if (d == 0) A6[(i0 + r0 + r) * HH + head] = v;
        }
    }
}

// ---------------------------------------------------------------------------
// Main fused kernel (unchanged from R15 — proven 23.8us).
// Grid 128 (I_TILE=8 rows each), block 512 = 16 warps.
// Warp w: head = w&3, js = w>>2; per t handles j = t*128+js*32+lane, all 8 i.
// r4/ra for stage t+1 prefetched before e-phase(t); adj mask from adj8_s
// (LDS.U8). e-phase fp16x2; agg on tensor pipe (ldmatrix + mma.m16n8k16).
// Max-free base-2 softmax; mask -> p = 0.
// ---------------------------------------------------------------------------
__global__ __launch_bounds__(512) void gat_main(
    const int*   __restrict__ adj,
    const float* __restrict__ a,
    const float* __restrict__ ln_g,
    const float* __restrict__ ln_b,
    float*       __restrict__ out)
{
    __shared__ __align__(16) __half l_sh[I_TILE * DIM];       // fp16 l rows
    __shared__ __align__(16) __half p_sh[16 * I_TILE * 32 + 32]; // + zero row
    __shared__ __align__(16) float  red_s[16 * I_TILE * 32];  // cross-warp acc
    __shared__ __align__(16) float  o_s[I_TILE * DIM];
    __shared__ float sl_s[16 * I_TILE];
    __shared__ unsigned char adj8_s[NN];                      // bit ii = adj

    int tid  = threadIdx.x;
    int w    = tid >> 5, lane = tid & 31;
    int head = w & 3,    js   = w >> 2;      // js in 0..3
    int i0   = blockIdx.x * I_TILE;

    // ---- pack this i-block's adjacency: 2 j per thread, coalesced ----
#pragma unroll
    for (int jj = 0; jj < 2; jj++) {
        int j = tid + jj * 512;
        unsigned bb = 0;
#pragma unroll
        for (int ii = 0; ii < 8; ii++)
            bb |= (__ldg(&adj[(i0 + ii) * NN + j]) != 0 ? 1u : 0u) << ii;
        adj8_s[j] = (unsigned char)bb;
    }

    // 0.4*log2e * a packed as 16 fp16x2 (d-pairs), warp-uniform in regs
    u32 ar2h[16];
#pragma unroll
    for (int s = 0; s < 16; s++) {
        __half2 hp = __floats2half2_rn((0.4f * LOG2E) * __ldg(&a[2 * s]),
                                       (0.4f * LOG2E) * __ldg(&a[2 * s + 1]));
        ar2h[s] = *reinterpret_cast<u32*>(&hp);
    }

    if (tid < 128)       // stage fp16 l rows: 8 x 256B
        reinterpret_cast<uint4*>(l_sh)[tid] =
            __ldg(&reinterpret_cast<const uint4*>(g_Lh)[i0 * (DIM / 8) + tid]);
    if (tid < 16)        // zero row for ldmatrix M-padding
        reinterpret_cast<u32*>(p_sh + 16 * 256)[tid] = 0u;

    float la[I_TILE], sl[I_TILE];
    float dacc[16];
#pragma unroll
    for (int ii = 0; ii < I_TILE; ii++) {
        la[ii] = __ldg(&g_La6[(i0 + ii) * HH + head]);
        sl[ii] = 0.f;
    }
#pragma unroll
    for (int k = 0; k < 16; k++) dacc[k] = 0.f;
    __syncthreads();   // l_sh + zero row + adj8_s visible

    const uint4* Rh4 = reinterpret_cast<const uint4*>(g_Rh);
    __half* myph = &p_sh[w * 256];
    int lg = lane >> 3, lr = lane & 7;       // ldmatrix tile group / row

    // preload r-side for stage 0
    uint4 r4[4];
    float ra;
    {
        int jcol = js * 32 + lane;
#pragma unroll
        for (int qg = 0; qg < 4; qg++)
            r4[qg] = __ldg(&Rh4[(head * 4 + qg) * NN + jcol]);
        ra = __ldg(&g_Ra6[jcol * HH + head]);
    }

    for (int t = 0; t < 8; t++) {
        int jcol = t * 128 + js * 32 + lane;
        int jb0  = t * 8 + js * 2;               // first 16-j block
        unsigned b = adj8_s[jcol];               // LDS.U8

        // ---- B-fragment loads for stage t (consumed after e-phase: hidden) ----
        uint2 bq[8];
#pragma unroll
        for (int ks = 0; ks < 2; ks++)
#pragma unroll
            for (int nt = 0; nt < 4; nt++)
                bq[ks * 4 + nt] = __ldg(reinterpret_cast<const uint2*>(
                    &g_Vf[(((head * 64 + jb0 + ks) * 4 + nt) * 32 + lane) * 2]));

        // ---- prefetch r-side for stage t+1 (consumed one e-phase later) ----
        uint4 r4n[4];
        float ran = 0.f;
        if (t < 7) {
            int jn = (t + 1) * 128 + js * 32 + lane;
#pragma unroll
            for (int qg = 0; qg < 4; qg++)
                r4n[qg] = __ldg(&Rh4[(head * 4 + qg) * NN + jn]);
            ran = __ldg(&g_Ra6[jn * HH + head]);
        }

        // ---- e phase: fp16x2 HADD2 + abs(LOP) + HFMA2 ----
#pragma unroll
        for (int ii = 0; ii < I_TILE; ii++) {
            const uint4* lrow = reinterpret_cast<const uint4*>(&l_sh[ii * DIM + head * 32]);
            u32 ea0 = 0u, ea1 = 0u, ea2 = 0u, ea3 = 0u;   // half2 zeros
#pragma unroll
            for (int qg = 0; qg < 4; qg++) {
                uint4 l4 = lrow[qg];
                u32 y0, y1, y2, y3;
                HADD2(y0, l4.x, r4[qg].x);
                HADD2(y1, l4.y, r4[qg].y);
                HADD2(y2, l4.z, r4[qg].z);
                HADD2(y3, l4.w, r4[qg].w);
                y0 &= 0x7FFF7FFFu; y1 &= 0x7FFF7FFFu;     // |.| both halves (ALU)
                y2 &= 0x7FFF7FFFu; y3 &= 0x7FFF7FFFu;
                HFMA2(ea0, ar2h[qg * 4 + 0], y0);
                HFMA2(ea1, ar2h[qg * 4 + 1], y1);
                HFMA2(ea2, ar2h[qg * 4 + 2], y2);
                HFMA2(ea3, ar2h[qg * 4 + 3], y3);
            }
            HADD2(ea0, ea0, ea1);
            HADD2(ea2, ea2, ea3);
            HADD2(ea0, ea0, ea2);
            float2 f2 = __half22float2(*reinterpret_cast<__half2*>(&ea0));
            float e = (la[ii] + ra) + (f2.x + f2.y);
            float p;
            asm("ex2.approx.f32 %0, %1;" : "=f"(p) : "f"(e));
            p = (b & (1u << ii)) ? p : 0.f;
            sl[ii] += p;
            myph[ii * 32 + lane] = __float2half_rn(p);
        }
        __syncwarp();

        // ---- agg phase on tensor pipe: ldmatrix + mma.m16n8k16 ----
#pragma unroll
        for (int ks = 0; ks < 2; ks++) {
            const __half* ap = (lg & 1) ? (p_sh + 16 * 256)
                                        : (myph + lr * 32 + ks * 16 + (lg >> 1) * 8);
            u32 sa = (u32)__cvta_generic_to_shared(ap);
            u32 a0, a1, a2, a3;
            asm volatile("ldmatrix.sync.aligned.m8n8.x4.shared.b16 {%0,%1,%2,%3}, [%4];"
                         : "=r"(a0), "=r"(a1), "=r"(a2), "=r"(a3) : "r"(sa));
#pragma unroll
            for (int nt = 0; nt < 4; nt++)
                MMA16816(dacc[nt * 4 + 0], dacc[nt * 4 + 1],
                         dacc[nt * 4 + 2], dacc[nt * 4 + 3],
                         a0, a1, a2, a3, bq[ks * 4 + nt].x, bq[ks * 4 + nt].y);
        }
        __syncwarp();   // LDSM consumed before next stage's STS overwrites p

        // rotate prefetched r-side into place
        if (t < 7) {
#pragma unroll
            for (int qg = 0; qg < 4; qg++) r4[qg] = r4n[qg];
            ra = ran;
        }
    }

    // ---- cross-warp (js) reduction ----
#pragma unroll
    for (int ii = 0; ii < I_TILE; ii++) {
        float S = sl[ii];
#pragma unroll
        for (int o = 16; o; o >>= 1) S += __shfl_xor_sync(0xffffffffu, S, o);
        if (lane == 0) sl_s[w * I_TILE + ii] = S;
    }
    // write mma accumulators: lane holds (ii = lane/4, d = nt*8 + 2*(lane%4)+{0,1})
    {
        int iw = lane >> 2, db = 2 * (lane & 3);
        float* myred = &red_s[w * 256];
#pragma unroll
        for (int nt = 0; nt < 4; nt++) {
            myred[iw * 32 + nt * 8 + db]     = dacc[nt * 4 + 0];
            myred[iw * 32 + nt * 8 + db + 1] = dacc[nt * 4 + 1];
        }
    }
    __syncthreads();

    // warp w: head' = w&3, covers ii = (w>>2) and (w>>2)+4
#pragma unroll
    for (int r = 0; r < 2; r++) {
        int ii = (w >> 2) + r * 4;
        int hh = w & 3;
        float acc = 0.f, S = 0.f;
#pragma unroll
        for (int g = 0; g < 4; g++) {
            acc += red_s[((g * 4 + hh) * I_TILE + ii) * 32 + lane];
            S   += sl_s[(g * 4 + hh) * I_TILE + ii];
        }
        o_s[ii * DIM + hh * 32 + lane] = acc * __frcp_rn(S);
    }
    __syncthreads();

    // LayerNorm + ReLU: warps 0..7 handle rows 0..7
    if (w < I_TILE) {
        int i = w;
        float v0 = o_s[i * DIM + lane];
        float v1 = o_s[i * DIM + 32 + lane];
        float v2 = o_s[i * DIM + 64 + lane];
        float v3 = o_s[i * DIM + 96 + lane];
        float sm = (v0 + v1) + (v2 + v3);
        float sq = v0 * v0 + v1 * v1 + v2 * v2 + v3 * v3;
#pragma unroll
        for (int o = 16; o; o >>= 1) {
            sm += __shfl_xor_sync(0xffffffffu, sm, o);
            sq += __shfl_xor_sync(0xffffffffu, sq, o);
        }
        float mean = sm * (1.f / 128.f);
        float var  = sq * (1.f / 128.f) - mean * mean;
        float rstd = rsqrtf(var + 1e-5f);
        float vals[4] = {v0, v1, v2, v3};
#pragma unroll
        for (int k = 0; k < 4; k++) {
            int c = 32 * k + lane;
            float y = (vals[k] - mean) * rstd * __ldg(&ln_g[c]) + __ldg(&ln_b[c]);
            out[(i0 + i) * DIM + c] = fmaxf(y, 0.f);
        }
    }
}

extern "C" void kernel_launch(void* const* d_in, const int* in_sizes, int n_in,
                              void* d_out, int out_size)
{
    const float* h   = (const float*)d_in[0];
    const int*   adj = (const int*)  d_in[1];
    const float* Wl  = (const float*)d_in[2];
    const float* Wr  = (const float*)d_in[3];
    const float* Wv  = (const float*)d_in[4];
    const float* a   = (const float*)d_in[5];
    const float* g   = (const float*)d_in[6];
    const float* b   = (const float*)d_in[7];

    const int prep_smem = (DIM * DIM + 16 * DIM) * sizeof(float);  // 72KB
    static int configured = 0;
    if (!configured) {
        cudaFuncSetAttribute(prep_kernel,
                             cudaFuncAttributeMaxDynamicSharedMemorySize, prep_smem);
        configured = 1;
    }

    prep_kernel<<<dim3(64, 3), 256, prep_smem>>>(h, Wl, Wr, Wv, a);
    gat_main<<<NN / I_TILE, 512>>>(adj, a, g, b, (float*)d_out);
}